// round 17
// baseline (speedup 1.0000x reference)
#include <cuda_runtime.h>
#include <cuda_fp16.h>
#include <stdint.h>
#include <math.h>

#define N_NODES 50000
#define N_EDGES 800000
#define F_IN    512
#define HID     256
#define NCLS    40
#define WDIM    50

// ------------------------- scratch (device globals) -------------------------
__device__ float  g_h   [(size_t)N_NODES * HID];    // h1 f32
__device__ __half g_hh  [(size_t)N_NODES * HID];    // h1/segsum fp16
__device__ float  g_e   [(size_t)N_EDGES * NCLS];   // layer-2 exp(ow) [E,40] f32
__device__ __half g_eh  [(size_t)N_EDGES * HID];    // layer-1 exp(ow) [E,256] fp16
__device__ float  g_sum [(size_t)N_NODES * HID];    // softmax denominators
__device__ float  g_out1[(size_t)N_NODES * HID];    // layer-1 aggregated output
__device__ __half g_o1h [(size_t)N_NODES * HID];    // elu(out1) fp16
__device__ float  g_h2  [(size_t)N_NODES * NCLS];   // h2 (then /= segsum)
__device__ __half g_w1h [(size_t)HID * HID];        // m1_w1^T fp16 [n][k]
__device__ __half g_w0h [(size_t)HID * 64];         // m1_w0^T fp16 [n][k pad 64]
__device__ __half g_xh  [(size_t)N_NODES * F_IN];   // x fp16
__device__ __half g_W1t [(size_t)HID * F_IN];       // W1^T fp16 [n][k]
__device__ __half g_W2t [(size_t)64 * HID];         // W2^T fp16 [n pad 64][k=256]
__device__ __half g_w0h2[(size_t)64 * 64];          // m2_w0^T fp16 [n pad 64][k pad 64]
__device__ __half g_w1h2[(size_t)64 * 48];          // m2_w1^T fp16 [n pad 64][k pad 48]

// --------------------------- vector reductions ------------------------------
__device__ __forceinline__ void red_add_v4(float* p, float a, float b, float c, float d) {
    asm volatile("red.global.add.v4.f32 [%0], {%1,%2,%3,%4};"
                 :: "l"(p), "f"(a), "f"(b), "f"(c), "f"(d) : "memory");
}
__device__ __forceinline__ void red_add_v2(float* p, float a, float b) {
    asm volatile("red.global.add.v2.f32 [%0], {%1,%2};"
                 :: "l"(p), "f"(a), "f"(b) : "memory");
}

// ------------------------------- utilities ---------------------------------
__global__ void zero_k(float* __restrict__ p, int n) {
    int i = blockIdx.x * blockDim.x + threadIdx.x;
    if (i < n) p[i] = 0.0f;
}

__global__ void div_k(float* __restrict__ h, const float* __restrict__ s, int n) {
    int i = blockIdx.x * blockDim.x + threadIdx.x;
    if (i < n) h[i] = h[i] / s[i];
}

__global__ void div_conv(const float* __restrict__ h, const float* __restrict__ s,
                         __half* __restrict__ hh, int n) {
    int i = blockIdx.x * blockDim.x + threadIdx.x;
    if (i < n) hh[i] = __float2half(h[i] / s[i]);
}

__global__ void elu_conv(const float* __restrict__ a, __half* __restrict__ o, int n) {
    int i = blockIdx.x * blockDim.x + threadIdx.x;
    if (i < n) {
        float v = a[i];
        o[i] = __float2half(v > 0.f ? v : expm1f(v));
    }
}

__global__ void conv_x(const float* __restrict__ x, __half* __restrict__ xh, int n4) {
    int i = blockIdx.x * blockDim.x + threadIdx.x;
    if (i < n4) {
        float4 v = *(const float4*)&x[i * 4];
        __half2* d = (__half2*)&xh[i * 4];
        d[0] = __floats2half2_rn(v.x, v.y);
        d[1] = __floats2half2_rn(v.z, v.w);
    }
}

template<int K, int N, int KP, int NP>
__global__ void conv_wt(const float* __restrict__ w, __half* __restrict__ wt) {
    int i = blockIdx.x * 256 + threadIdx.x;
    if (i >= NP * KP) return;
    int n = i / KP, k = i % KP;
    wt[i] = (k < K && n < N) ? __float2half(w[k * N + n]) : __half(0.0f);
}

// ------------------------------ mma helpers ---------------------------------
__device__ __forceinline__ void mma16816(float c[4], const unsigned int a[4],
                                         unsigned int b0, unsigned int b1) {
    asm volatile(
        "mma.sync.aligned.m16n8k16.row.col.f32.f16.f16.f32 "
        "{%0,%1,%2,%3}, {%4,%5,%6,%7}, {%8,%9}, {%0,%1,%2,%3};\n"
        : "+f"(c[0]), "+f"(c[1]), "+f"(c[2]), "+f"(c[3])
        : "r"(a[0]), "r"(a[1]), "r"(a[2]), "r"(a[3]), "r"(b0), "r"(b1));
}

__device__ __forceinline__ unsigned int sm_addr(const void* p) {
    return (unsigned int)__cvta_generic_to_shared(p);
}
__device__ __forceinline__ void ldsm4(unsigned int r[4], unsigned int addr) {
    asm volatile("ldmatrix.sync.aligned.m8n8.x4.shared.b16 {%0,%1,%2,%3}, [%4];"
                 : "=r"(r[0]), "=r"(r[1]), "=r"(r[2]), "=r"(r[3]) : "r"(addr));
}
__device__ __forceinline__ unsigned int cvt2(const float* p) {
    float2 v = *(const float2*)p;
    __half2 h = __floats2half2_rn(v.x, v.y);
    return *reinterpret_cast<unsigned int*>(&h);
}
__device__ __forceinline__ unsigned int pack2(float a, float b) {
    __half2 h = __floats2half2_rn(a, b);
    return *reinterpret_cast<unsigned int*>(&h);
}
__device__ __forceinline__ float prelu1(float v, float a) {
    return v >= 0.f ? v : a * v;
}

// ====== tensor-core node GEMM: out[M][NSTORE] = A@B^T + bias (N padded) =====
template<int K, int N, int NSTORE>
__global__ void __launch_bounds__(256)
node_gemm_tc(const __half* __restrict__ A, const __half* __restrict__ Bt,
             const float* __restrict__ bias, float* __restrict__ out, int M)
{
    constexpr int BM = 128, BK = 64, KS = 72;
    __shared__ __half As[BM * KS];
    __shared__ __half Bs[64 * KS];

    const int tid = threadIdx.x;
    const int lane = tid & 31, warp = tid >> 5;
    const int g = lane >> 2, t2 = (lane & 3) * 2;
    const int wm = warp >> 2, wn = warp & 3;
    const int rBase = blockIdx.x * BM;
    const int cBase = blockIdx.y * 64;

    unsigned int aB[4], bB;
    #pragma unroll
    for (int mt = 0; mt < 4; mt++)
        aB[mt] = sm_addr(&As[(wm * 64 + mt * 16 + (lane & 15)) * KS + ((lane >> 4) << 3)]);
    bB = sm_addr(&Bs[(wn * 16 + ((lane >> 4) << 3) + (lane & 7)) * KS + (((lane >> 3) & 1) << 3)]);

    float c[4][2][4];
    #pragma unroll
    for (int mt = 0; mt < 4; mt++)
        #pragma unroll
        for (int nt = 0; nt < 2; nt++)
            { c[mt][nt][0]=0.f; c[mt][nt][1]=0.f; c[mt][nt][2]=0.f; c[mt][nt][3]=0.f; }

    for (int k0 = 0; k0 < K; k0 += BK) {
        #pragma unroll
        for (int i = 0; i < 4; i++) {
            int idx = tid + i * 256;
            int row = idx >> 3, seg = idx & 7;
            int gr = rBase + row;
            uint4 v = make_uint4(0u, 0u, 0u, 0u);
            if (gr < M) v = *(const uint4*)&A[(size_t)gr * K + k0 + seg * 8];
            *(uint4*)&As[row * KS + seg * 8] = v;
        }
        #pragma unroll
        for (int i = 0; i < 2; i++) {
            int idx = tid + i * 256;
            int n = idx >> 3, seg = idx & 7;
            *(uint4*)&Bs[n * KS + seg * 8] =
                *(const uint4*)&Bt[(size_t)(cBase + n) * K + k0 + seg * 8];
        }
        __syncthreads();

        #pragma unroll
        for (int ks = 0; ks < 4; ks++) {
            unsigned int b[4];
            ldsm4(b, bB + ks * 32);
            #pragma unroll
            for (int mt = 0; mt < 4; mt++) {
                unsigned int a[4];
                ldsm4(a, aB[mt] + ks * 32);
                mma16816(c[mt][0], a, b[0], b[1]);
                mma16816(c[mt][1], a, b[2], b[3]);
            }
        }
        __syncthreads();
    }

    #pragma unroll
    for (int mt = 0; mt < 4; mt++) {
        int r0 = rBase + wm * 64 + mt * 16 + g;
        #pragma unroll
        for (int nt = 0; nt < 2; nt++) {
            int col = cBase + wn * 16 + nt * 8 + t2;
            if (col < NSTORE) {
                float2 bb = *(const float2*)&bias[col];
                if (r0 < M)
                    *(float2*)&out[(size_t)r0 * NSTORE + col] =
                        make_float2(c[mt][nt][0] + bb.x, c[mt][nt][1] + bb.y);
                if (r0 + 8 < M)
                    *(float2*)&out[(size_t)(r0 + 8) * NSTORE + col] =
                        make_float2(c[mt][nt][2] + bb.x, c[mt][nt][3] + bb.y);
            }
        }
    }
}

// ========== layer-1 edge MLP: barrier-free, warp = 32 edges x 64 cols =======
// grid = (E1_BLK, 4): blockIdx.y picks a 64-col quarter of the 256 outputs.
// Two 16-edge A-sets share every B-fragment LDSM (stage-1 and stage-2),
// halving smem traffic per edge vs the 16-edge version.
#define E1_BLK  400
#define E1_SMEM ((64*264 + 256*72) * 2)

__global__ void __launch_bounds__(512, 1)
edge_mlp_tc(const float* __restrict__ wmul, const int* __restrict__ src,
            const __half* __restrict__ w0h, const float* __restrict__ pa,
            const __half* __restrict__ w1h, const float* __restrict__ b1,
            __half* __restrict__ eout, float* __restrict__ segsum)
{
    extern __shared__ char smraw[];
    __half* sB  = (__half*)smraw;          // [64][264] w1^T rows colOff..+64
    __half* sB0 = sB + 64 * 264;           // [256][72] w0^T (full)

    const int tid  = threadIdx.x;
    const int lane = tid & 31, warp = tid >> 5;   // 16 warps
    const int g = lane >> 2, t2 = (lane & 3) * 2;
    const int colOff = blockIdx.y * 64;

    for (int idx = tid; idx < 64 * 32; idx += 512) {
        int n = idx >> 5, kc = (idx & 31) * 8;
        *(uint4*)&sB[n * 264 + kc] = *(const uint4*)&w1h[(size_t)(colOff + n) * HID + kc];
    }
    for (int idx = tid; idx < 256 * 8; idx += 512) {
        int n = idx >> 3, kc = (idx & 7) * 8;
        *(uint4*)&sB0[n * 72 + kc] = *(const uint4*)&w0h[n * 64 + kc];
    }
    __syncthreads();

    const int br = ((lane >> 4) << 3) + (lane & 7);
    const int bh = ((lane >> 3) & 1) << 3;
    const unsigned int bS1 = sm_addr(&sB0[br * 72  + bh]);
    const unsigned int bS2 = sm_addr(&sB [br * 264 + bh]);

    for (int u = blockIdx.x * 16 + warp; u < N_EDGES / 32; u += E1_BLK * 16) {
        int e0 = u * 32;

        // ---- two A-fragment sets (wmul, fp32->fp16) straight from global ----
        unsigned int a[2][4][4];
        #pragma unroll
        for (int s = 0; s < 2; s++) {
            const float* wr0 = wmul + (size_t)(e0 + s * 16 + g) * WDIM;
            const float* wr1 = wr0 + 8 * WDIM;
            #pragma unroll
            for (int kb = 0; kb < 3; kb++) {
                a[s][kb][0] = cvt2(wr0 + kb * 16 + t2);
                a[s][kb][1] = cvt2(wr1 + kb * 16 + t2);
                a[s][kb][2] = cvt2(wr0 + kb * 16 + 8 + t2);
                a[s][kb][3] = cvt2(wr1 + kb * 16 + 8 + t2);
            }
            a[s][3][0] = (t2 == 0) ? cvt2(wr0 + 48) : 0u;
            a[s][3][1] = (t2 == 0) ? cvt2(wr1 + 48) : 0u;
            a[s][3][2] = 0u; a[s][3][3] = 0u;
        }

        float c2[2][8][4];
        #pragma unroll
        for (int s = 0; s < 2; s++)
            #pragma unroll
            for (int nt = 0; nt < 8; nt++)
                { c2[s][nt][0]=0.f; c2[s][nt][1]=0.f; c2[s][nt][2]=0.f; c2[s][nt][3]=0.f; }

        #pragma unroll
        for (int ks = 0; ks < 16; ks++) {
            // stage 1: t cols [16ks, 16ks+16) for both edge sets; shared B
            float c1[2][2][4] = {{{0.f,0.f,0.f,0.f},{0.f,0.f,0.f,0.f}},
                                 {{0.f,0.f,0.f,0.f},{0.f,0.f,0.f,0.f}}};
            #pragma unroll
            for (int kb = 0; kb < 4; kb++) {
                unsigned int b[4];
                ldsm4(b, bS1 + ks * 2304 + kb * 32);   // 2304 = 16*72*2
                #pragma unroll
                for (int s = 0; s < 2; s++) {
                    mma16816(c1[s][0], a[s][kb], b[0], b[1]);
                    mma16816(c1[s][1], a[s][kb], b[2], b[3]);
                }
            }
            // prelu + pack: C fragment == stage-2 A fragment layout
            float2 al0 = *(const float2*)&pa[ks * 16 + t2];
            float2 al1 = *(const float2*)&pa[ks * 16 + 8 + t2];
            unsigned int aa[2][4];
            #pragma unroll
            for (int s = 0; s < 2; s++) {
                aa[s][0] = pack2(prelu1(c1[s][0][0], al0.x), prelu1(c1[s][0][1], al0.y));
                aa[s][1] = pack2(prelu1(c1[s][0][2], al0.x), prelu1(c1[s][0][3], al0.y));
                aa[s][2] = pack2(prelu1(c1[s][1][0], al1.x), prelu1(c1[s][1][1], al1.y));
                aa[s][3] = pack2(prelu1(c1[s][1][2], al1.x), prelu1(c1[s][1][3], al1.y));
            }
            // stage 2: 64 output cols; B shared across both edge sets
            #pragma unroll
            for (int pr = 0; pr < 4; pr++) {
                unsigned int b[4];
                ldsm4(b, bS2 + pr * 8448 + ks * 32);   // 8448 = 16*264*2
                #pragma unroll
                for (int s = 0; s < 2; s++) {
                    mma16816(c2[s][2 * pr],     aa[s], b[0], b[1]);
                    mma16816(c2[s][2 * pr + 1], aa[s], b[2], b[3]);
                }
            }
        }

        // ---- epilogue: e = exp(ow + b1) fp16; segsum[src] += e ----
        #pragma unroll
        for (int s = 0; s < 2; s++) {
            int ea = e0 + s * 16 + g, eb = ea + 8;
            int s0 = src[ea], s1 = src[eb];
            #pragma unroll
            for (int nt = 0; nt < 8; nt++) {
                int col = colOff + nt * 8 + t2;
                float2 bb = *(const float2*)&b1[col];
                float v0 = __expf(c2[s][nt][0] + bb.x);
                float v1 = __expf(c2[s][nt][1] + bb.y);
                float v2 = __expf(c2[s][nt][2] + bb.x);
                float v3 = __expf(c2[s][nt][3] + bb.y);
                *(__half2*)&eout[(size_t)ea * HID + col] = __floats2half2_rn(v0, v1);
                *(__half2*)&eout[(size_t)eb * HID + col] = __floats2half2_rn(v2, v3);
                red_add_v2(&segsum[(size_t)s0 * HID + col], v0, v1);
                red_add_v2(&segsum[(size_t)s1 * HID + col], v2, v3);
            }
        }
    }
}

// ========== layer-2 edge MLP: barrier-free, warp = 16 edges x 40(64) cols ===
#define E2_BLK 400

__global__ void __launch_bounds__(512, 1)
edge_mlp_tc2(const float* __restrict__ wmul, const int* __restrict__ src,
             const __half* __restrict__ w0h2, const float* __restrict__ pa,
             const __half* __restrict__ w1h2, const float* __restrict__ b1,
             float* __restrict__ eout, float* __restrict__ segsum)
{
    __shared__ __half sB0[48 * 72];   // w0^T rows 0..47 (t cols, pad 48)
    __shared__ __half sB1[64 * 56];   // w1^T [64 out-cols][48 k]

    const int tid  = threadIdx.x;
    const int lane = tid & 31, warp = tid >> 5;
    const int g = lane >> 2, t2 = (lane & 3) * 2;

    for (int idx = tid; idx < 48 * 8; idx += 512) {
        int n = idx >> 3, kc = (idx & 7) * 8;
        *(uint4*)&sB0[n * 72 + kc] = *(const uint4*)&w0h2[n * 64 + kc];
    }
    for (int idx = tid; idx < 64 * 6; idx += 512) {
        int n = idx / 6, kc = (idx % 6) * 8;
        *(uint4*)&sB1[n * 56 + kc] = *(const uint4*)&w1h2[n * 48 + kc];
    }
    __syncthreads();

    const int br = ((lane >> 4) << 3) + (lane & 7);
    const int bh = ((lane >> 3) & 1) << 3;
    const unsigned int bS1 = sm_addr(&sB0[br * 72 + bh]);
    const unsigned int bS2 = sm_addr(&sB1[br * 56 + bh]);

    for (int u = blockIdx.x * 16 + warp; u < N_EDGES / 16; u += E2_BLK * 16) {
        int e0 = u * 16;

        const float* wr0 = wmul + (size_t)(e0 + g) * WDIM;
        const float* wr1 = wr0 + 8 * WDIM;
        unsigned int a[4][4];
        #pragma unroll
        for (int kb = 0; kb < 3; kb++) {
            a[kb][0] = cvt2(wr0 + kb * 16 + t2);
            a[kb][1] = cvt2(wr1 + kb * 16 + t2);
            a[kb][2] = cvt2(wr0 + kb * 16 + 8 + t2);
            a[kb][3] = cvt2(wr1 + kb * 16 + 8 + t2);
        }
        a[3][0] = (t2 == 0) ? cvt2(wr0 + 48) : 0u;
        a[3][1] = (t2 == 0) ? cvt2(wr1 + 48) : 0u;
        a[3][2] = 0u; a[3][3] = 0u;

        float c2[8][4];
        #pragma unroll
        for (int nt = 0; nt < 8; nt++)
            { c2[nt][0]=0.f; c2[nt][1]=0.f; c2[nt][2]=0.f; c2[nt][3]=0.f; }

        #pragma unroll
        for (int ks = 0; ks < 3; ks++) {
            float c1[2][4] = {{0.f,0.f,0.f,0.f},{0.f,0.f,0.f,0.f}};
            #pragma unroll
            for (int kb = 0; kb < 4; kb++) {
                unsigned int b[4];
                ldsm4(b, bS1 + ks * 2304 + kb * 32);
                mma16816(c1[0], a[kb], b[0], b[1]);
                mma16816(c1[1], a[kb], b[2], b[3]);
            }
            float2 al0 = *(const float2*)&pa[ks * 16 + t2];
            float2 al1 = (ks < 2) ? *(const float2*)&pa[ks * 16 + 8 + t2]
                                  : make_float2(0.f, 0.f);
            unsigned int aa[4];
            aa[0] = pack2(prelu1(c1[0][0], al0.x), prelu1(c1[0][1], al0.y));
            aa[1] = pack2(prelu1(c1[0][2], al0.x), prelu1(c1[0][3], al0.y));
            aa[2] = pack2(prelu1(c1[1][0], al1.x), prelu1(c1[1][1], al1.y));
            aa[3] = pack2(prelu1(c1[1][2], al1.x), prelu1(c1[1][3], al1.y));
            #pragma unroll
            for (int pr = 0; pr < 4; pr++) {
                unsigned int b[4];
                ldsm4(b, bS2 + pr * 1792 + ks * 32);   // 1792 = 16*56*2
                mma16816(c2[2 * pr],     aa, b[0], b[1]);
                mma16816(c2[2 * pr + 1], aa, b[2], b[3]);
            }
        }

        int ea = e0 + g, eb = ea + 8;
        int s0 = src[ea], s1 = src[eb];
        #pragma unroll
        for (int nt = 0; nt < 5; nt++) {              // cols 0..39 only
            int col = nt * 8 + t2;
            float2 bb = *(const float2*)&b1[col];
            float v0 = __expf(c2[nt][0] + bb.x);
            float v1 = __expf(c2[nt][1] + bb.y);
            float v2 = __expf(c2[nt][2] + bb.x);
            float v3 = __expf(c2[nt][3] + bb.y);
            *(float2*)&eout[(size_t)ea * NCLS + col] = make_float2(v0, v1);
            *(float2*)&eout[(size_t)eb * NCLS + col] = make_float2(v2, v3);
            red_add_v2(&segsum[(size_t)s0 * NCLS + col], v0, v1);
            red_add_v2(&segsum[(size_t)s1 * NCLS + col], v2, v3);
        }
    }
}

// ---------- message + scatter: out[dst] += e * hn[src]  (both fp16) --------
__global__ void msg256(const __half* __restrict__ ewh, const int* __restrict__ src,
                       const int* __restrict__ dst, const __half* __restrict__ hn,
                       float* __restrict__ out)
{
    int tid  = threadIdx.x;
    int eloc = tid >> 6;
    int c0   = (tid & 63) * 4;
    int edge = blockIdx.x * 4 + eloc;
    int s = src[edge], d = dst[edge];
    const __half2* ep = (const __half2*)&ewh[(size_t)edge * HID + c0];
    const __half2* hp = (const __half2*)&hn[(size_t)s * HID + c0];
    float2 e01 = __half22float2(ep[0]);
    float2 e23 = __half22float2(ep[1]);
    float2 h01 = __half22float2(hp[0]);
    float2 h23 = __half22float2(hp[1]);
    red_add_v4(&out[(size_t)d * HID + c0],
               e01.x * h01.x, e01.y * h01.y, e23.x * h23.x, e23.y * h23.y);
}

__global__ void msg40(const float* __restrict__ ew, const int* __restrict__ src,
                      const int* __restrict__ dst, const float* __restrict__ hn,
                      float* __restrict__ out)
{
    int tid  = threadIdx.x;
    int eloc = tid / 10;
    int c0   = (tid % 10) * 4;
    int edge = blockIdx.x * 32 + eloc;
    int s = src[edge], d = dst[edge];
    float4 ev = *(const float4*)&ew[(size_t)edge * NCLS + c0];
    float4 hv = *(const float4*)&hn[(size_t)s    * NCLS + c0];
    red_add_v4(&out[(size_t)d * NCLS + c0],
               ev.x * hv.x, ev.y * hv.y, ev.z * hv.z, ev.w * hv.w);
}

// --------------------------- in-place log_softmax ---------------------------
__global__ void logsoftmax40(float* __restrict__ out, int M)
{
    int warp = (blockIdx.x * blockDim.x + threadIdx.x) >> 5;
    int lane = threadIdx.x & 31;
    if (warp >= M) return;
    float* row = out + (size_t)warp * NCLS;
    float v0 = row[lane];
    float v1 = (lane < 8) ? row[32 + lane] : -INFINITY;
    float m = fmaxf(v0, v1);
    #pragma unroll
    for (int o = 16; o; o >>= 1) m = fmaxf(m, __shfl_xor_sync(0xffffffffu, m, o));
    float s = expf(v0 - m) + ((lane < 8) ? expf(v1 - m) : 0.f);
    #pragma unroll
    for (int o = 16; o; o >>= 1) s += __shfl_xor_sync(0xffffffffu, s, o);
    float l = m + logf(s);
    row[lane] = v0 - l;
    if (lane < 8) row[32 + lane] = v1 - l;
}

// --------------------------------- launch -----------------------------------
extern "C" void kernel_launch(void* const* d_in, const int* in_sizes, int n_in,
                              void* d_out, int out_size)
{
    const float* x    = (const float*)d_in[0];
    const int*   ei   = (const int*)  d_in[1];
    const float* wmul = (const float*)d_in[2];
    const float* W1   = (const float*)d_in[3];
    const float* b1   = (const float*)d_in[4];
    const float* m1w0 = (const float*)d_in[5];
    const float* m1a  = (const float*)d_in[6];
    const float* m1w1 = (const float*)d_in[7];
    const float* m1b1 = (const float*)d_in[8];
    const float* W2   = (const float*)d_in[9];
    const float* b2   = (const float*)d_in[10];
    const float* m2w0 = (const float*)d_in[11];
    const float* m2a  = (const float*)d_in[12];
    const float* m2w1 = (const float*)d_in[13];
    const float* m2b1 = (const float*)d_in[14];
    float* out = (float*)d_out;

    const int* src = ei;            // edge_index[0]
    const int* dst = ei + N_EDGES;  // edge_index[1]

    float *p_h, *p_e, *p_sum, *p_out1, *p_h2;
    __half *p_w1h, *p_w0h, *p_xh, *p_W1t, *p_W2t, *p_eh, *p_w0h2, *p_w1h2, *p_hh, *p_o1h;
    cudaGetSymbolAddress((void**)&p_h,    g_h);
    cudaGetSymbolAddress((void**)&p_hh,   g_hh);
    cudaGetSymbolAddress((void**)&p_e,    g_e);
    cudaGetSymbolAddress((void**)&p_eh,   g_eh);
    cudaGetSymbolAddress((void**)&p_sum,  g_sum);
    cudaGetSymbolAddress((void**)&p_out1, g_out1);
    cudaGetSymbolAddress((void**)&p_o1h,  g_o1h);
    cudaGetSymbolAddress((void**)&p_h2,   g_h2);
    cudaGetSymbolAddress((void**)&p_w1h,  g_w1h);
    cudaGetSymbolAddress((void**)&p_w0h,  g_w0h);
    cudaGetSymbolAddress((void**)&p_xh,   g_xh);
    cudaGetSymbolAddress((void**)&p_W1t,  g_W1t);
    cudaGetSymbolAddress((void**)&p_W2t,  g_W2t);
    cudaGetSymbolAddress((void**)&p_w0h2, g_w0h2);
    cudaGetSymbolAddress((void**)&p_w1h2, g_w1h2);

    cudaFuncSetAttribute(edge_mlp_tc, cudaFuncAttributeMaxDynamicSharedMemorySize, E1_SMEM);

    const int n1 = N_NODES * HID;
    const int n2 = N_NODES * NCLS;

    // launches 1-3: minimal prerequisites for edge_mlp_tc (capture lands on #4)
    conv_wt<HID,  HID,  HID,  HID><<<(HID * HID + 255) / 256, 256>>>(m1w1, p_w1h);  // 1
    conv_wt<WDIM, HID,  64,   HID><<<(HID * 64  + 255) / 256, 256>>>(m1w0, p_w0h);  // 2
    zero_k<<<(n1 + 255) / 256, 256>>>(p_sum, n1);                                   // 3

    // 4: THE kernel — e = exp(prelu(wmul@w0,a)@w1 + b1) fp16, segsum[src] += e
    {
        dim3 grid(E1_BLK, 4);
        edge_mlp_tc<<<grid, 512, E1_SMEM>>>(wmul, src, p_w0h, m1a, p_w1h, m1b1, p_eh, p_sum);
    }

    // remaining conversions + h1 GEMM
    conv_x<<<(N_NODES * F_IN / 4 + 255) / 256, 256>>>(x, p_xh, N_NODES * F_IN / 4);
    conv_wt<F_IN, HID,  F_IN, HID><<<(HID * F_IN + 255) / 256, 256>>>(W1, p_W1t);
    conv_wt<HID,  NCLS, HID,  64 ><<<(64 * HID   + 255) / 256, 256>>>(W2, p_W2t);
    conv_wt<WDIM, NCLS, 64,   64 ><<<(64 * 64    + 255) / 256, 256>>>(m2w0, p_w0h2);
    conv_wt<NCLS, NCLS, 48,   64 ><<<(64 * 48    + 255) / 256, 256>>>(m2w1, p_w1h2);
    zero_k<<<(n1 + 255) / 256, 256>>>(p_out1, n1);

    // h1 = x @ W1 + b1  (tensor cores)
    {
        dim3 grid((N_NODES + 127) / 128, HID / 64);
        node_gemm_tc<F_IN, HID, HID><<<grid, 256>>>(p_xh, p_W1t, b1, p_h, N_NODES);
    }

    // hn = fp16(h1 / segsum)
    div_conv<<<(n1 + 255) / 256, 256>>>(p_h, p_sum, p_hh, n1);

    // out1[dst] += e * hn[src]
    msg256<<<N_EDGES / 4, 256>>>(p_eh, src, dst, p_hh, p_out1);

    // ---------------- layer 2 (C = 40) ----------------
    zero_k<<<(n2 + 255) / 256, 256>>>(p_sum, n2);
    zero_k<<<(n2 + 255) / 256, 256>>>(out,   n2);

    // h2 = elu(out1) @ W2 + b2  (tensor cores, N padded to 64)
    elu_conv<<<(n1 + 255) / 256, 256>>>(p_out1, p_o1h, n1);
    {
        dim3 grid((N_NODES + 127) / 128, 1);
        node_gemm_tc<HID, 64, NCLS><<<grid, 256>>>(p_o1h, p_W2t, b2, p_h2, N_NODES);
    }

    // layer-2 edge MLP (barrier-free tensor cores)
    edge_mlp_tc2<<<E2_BLK, 512>>>(wmul, src, p_w0h2, m2a, p_w1h2, m2b1, p_e, p_sum);

    // hn2 = h2 / segsum (in place)
    div_k<<<(n2 + 255) / 256, 256>>>(p_h2, p_sum, n2);

    msg40<<<N_EDGES / 32, 320>>>(p_e, src, dst, p_h2, out);

    logsoftmax40<<<(N_NODES + 7) / 8, 256>>>(out, N_NODES);
}